// round 4
// baseline (speedup 1.0000x reference)
#include <cuda_runtime.h>
#include <cstdint>
#include <math_constants.h>

#define NS   16
#define NP   2048
#define DIMS 64
#define KNN  16
#define IM   64            // i-rows per CTA (4 warps x 16)
#define JT   64            // j-rows per tile
#define NJT  (NP / JT)     // 32 tiles
#define BST  68            // padded B row stride (floats): conflict-free frags

static __device__ __forceinline__ uint32_t tf32b(float x) {
    uint32_t r;
    asm("cvt.rna.tf32.f32 %0, %1;" : "=r"(r) : "f"(x));
    return r;
}
static __device__ __forceinline__ void mma8(float c[4], const uint32_t a[4],
                                            uint32_t b0, uint32_t b1) {
    asm("mma.sync.aligned.m16n8k8.row.col.f32.tf32.tf32.f32 "
        "{%0,%1,%2,%3}, {%4,%5,%6,%7}, {%8,%9}, {%0,%1,%2,%3};"
        : "+f"(c[0]), "+f"(c[1]), "+f"(c[2]), "+f"(c[3])
        : "r"(a[0]), "r"(a[1]), "r"(a[2]), "r"(a[3]), "r"(b0), "r"(b1));
}

// replace-max insert into unsorted top-K (lexicographic (dist, idx))
static __device__ __forceinline__ void insert16(float bd[KNN], int bidx[KNN],
                                                float& worst, int& wslot,
                                                float d, int j) {
    if ((d < worst) | ((d == worst) & (j < 0))) {}  // no-op; keep strict filter below
    if (d < worst) {
        #pragma unroll
        for (int k = 0; k < KNN; ++k)
            if (k == wslot) { bd[k] = d; bidx[k] = j; }
        float mv = bd[0]; int mj = bidx[0]; int ms = 0;
        #pragma unroll
        for (int k = 1; k < KNN; ++k) {
            bool g = (bd[k] > mv) || (bd[k] == mv && bidx[k] > mj);
            if (g) { mv = bd[k]; mj = bidx[k]; ms = k; }
        }
        worst = mv; wslot = ms;
    }
}

__global__ __launch_bounds__(128, 2)
void knn_hmma_kernel(const float* __restrict__ h, float* __restrict__ out) {
    __shared__ float Bhi[JT][BST];
    __shared__ float Blo[JT][BST];
    __shared__ float sx2j[JT];
    __shared__ float sx2i[IM];

    const int tid  = threadIdx.x;
    const int lane = tid & 31;
    const int w    = tid >> 5;
    const int q    = lane & 3;          // tid-in-quad
    const int g    = lane >> 2;         // group id 0..7
    const int b    = blockIdx.x;
    const int i0   = blockIdx.y * IM;
    const float* __restrict__ hb = h + (size_t)b * NP * DIMS;

    // ---- sx2i: full-precision ||h_i||^2 for the CTA's 64 rows (2 threads/row) ----
    {
        const int r = tid >> 1, half = tid & 1;
        const float4* gp = reinterpret_cast<const float4*>(hb + (size_t)(i0 + r) * DIMS) + half * 8;
        float s = 0.0f;
        #pragma unroll
        for (int d = 0; d < 8; ++d) {
            float4 v = gp[d];
            s += v.x * v.x + v.y * v.y + v.z * v.z + v.w * v.w;
        }
        s += __shfl_xor_sync(0xffffffffu, s, 1);
        if (half == 0) sx2i[r] = s;
    }

    // ---- A fragments straight into registers (hi/lo tf32 split) ----
    const int ra = i0 + w * 16 + g;      // this thread's two i-rows
    const int rb = ra + 8;
    uint32_t Ahi[8][4], Alo[8][4];
    #pragma unroll
    for (int m = 0; m < 16; ++m) {       // col = q + 4m = kt*8 + q (+4 if m odd)
        const int kt = m >> 1, sl = (m & 1) ? 2 : 0;
        float xa = hb[(size_t)ra * DIMS + q + 4 * m];
        float xb = hb[(size_t)rb * DIMS + q + 4 * m];
        uint32_t ha = tf32b(xa), hbb = tf32b(xb);
        Ahi[kt][sl]     = ha;
        Ahi[kt][sl + 1] = hbb;
        Alo[kt][sl]     = tf32b(xa - __uint_as_float(ha));
        Alo[kt][sl + 1] = tf32b(xb - __uint_as_float(hbb));
    }
    __syncthreads();
    const float x2a = sx2i[w * 16 + g];
    const float x2b = sx2i[w * 16 + g + 8];

    // ---- two partial top-16 lists (rows ra, rb over this thread's col subset) ----
    float Ad[KNN], Bd[KNN]; int Ai[KNN], Bi[KNN];
    #pragma unroll
    for (int k = 0; k < KNN; ++k) {
        Ad[k] = CUDART_INF_F; Ai[k] = 0x7fffffff;
        Bd[k] = CUDART_INF_F; Bi[k] = 0x7fffffff;
    }
    float wA = CUDART_INF_F, wB = CUDART_INF_F; int sA = 0, sB = 0;

    for (int t = 0; t < NJT; ++t) {
        const int j0 = t * JT;
        __syncthreads();                 // previous tile fully consumed
        // ---- load B tile: fp32 -> (hi, lo) tf32 + row sumsq (2 threads/row) ----
        {
            const int r = tid >> 1, half = tid & 1;
            const float4* gp = reinterpret_cast<const float4*>(hb + (size_t)(j0 + r) * DIMS) + half * 8;
            float s = 0.0f;
            #pragma unroll
            for (int d = 0; d < 8; ++d) {
                float4 v = gp[d];
                s += v.x * v.x + v.y * v.y + v.z * v.z + v.w * v.w;
                uint32_t h0 = tf32b(v.x), h1 = tf32b(v.y), h2 = tf32b(v.z), h3 = tf32b(v.w);
                const int c0 = half * 32 + d * 4;
                *reinterpret_cast<float4*>(&Bhi[r][c0]) = make_float4(
                    __uint_as_float(h0), __uint_as_float(h1),
                    __uint_as_float(h2), __uint_as_float(h3));
                *reinterpret_cast<float4*>(&Blo[r][c0]) = make_float4(
                    __uint_as_float(tf32b(v.x - __uint_as_float(h0))),
                    __uint_as_float(tf32b(v.y - __uint_as_float(h1))),
                    __uint_as_float(tf32b(v.z - __uint_as_float(h2))),
                    __uint_as_float(tf32b(v.w - __uint_as_float(h3))));
            }
            s += __shfl_xor_sync(0xffffffffu, s, 1);
            if (half == 0) sx2j[r] = s;
        }
        __syncthreads();

        // ---- 3xTF32 MMA: C = Ahi*Bhi + Ahi*Blo + Alo*Bhi ----
        float c[8][4];
        #pragma unroll
        for (int nt = 0; nt < 8; ++nt) { c[nt][0] = c[nt][1] = c[nt][2] = c[nt][3] = 0.f; }

        #pragma unroll
        for (int pass = 0; pass < 3; ++pass) {
            const uint32_t (*Af)[4]   = (pass == 2) ? Alo : Ahi;
            const float (*Bs)[BST]    = (pass == 1) ? Blo : Bhi;
            #pragma unroll
            for (int nt = 0; nt < 8; ++nt) {
                const float* br = Bs[nt * 8 + g];
                #pragma unroll
                for (int kt = 0; kt < 8; ++kt) {
                    uint32_t b0 = __float_as_uint(br[kt * 8 + q]);
                    uint32_t b1 = __float_as_uint(br[kt * 8 + q + 4]);
                    mma8(c[nt], Af[kt], b0, b1);
                }
            }
        }

        // ---- fused epilogue: distances + filtered insert ----
        #pragma unroll
        for (int nt = 0; nt < 8; ++nt) {
            const int jc = j0 + nt * 8 + 2 * q;
            const float2 xj = *reinterpret_cast<const float2*>(&sx2j[nt * 8 + 2 * q]);
            float d0 = fmaf(-2.0f, c[nt][0], x2a + xj.x);
            float d1 = fmaf(-2.0f, c[nt][1], x2a + xj.y);
            float d2 = fmaf(-2.0f, c[nt][2], x2b + xj.x);
            float d3 = fmaf(-2.0f, c[nt][3], x2b + xj.y);
            insert16(Ad, Ai, wA, sA, d0, jc);
            insert16(Ad, Ai, wA, sA, d1, jc + 1);
            insert16(Bd, Bi, wB, sB, d2, jc);
            insert16(Bd, Bi, wB, sB, d3, jc + 1);
        }
    }

    // ---- merge the 4 per-quad partials per row via smem (alias B tile) ----
    __syncthreads();
    float* mdist = &Bhi[0][0];           // [64 rows][64 entries]
    int*   midx  = reinterpret_cast<int*>(&Blo[0][0]);
    {
        const int rowA = w * 16 + g, rowB = rowA + 8;
        #pragma unroll
        for (int k = 0; k < KNN; ++k) {
            mdist[rowA * 64 + q * 16 + k] = Ad[k];
            midx [rowA * 64 + q * 16 + k] = Ai[k];
            mdist[rowB * 64 + q * 16 + k] = Bd[k];
            midx [rowB * 64 + q * 16 + k] = Bi[k];
        }
    }
    __syncthreads();

    if (tid < IM) {
        const int r = tid;
        float fd[KNN]; int fi[KNN];
        #pragma unroll
        for (int k = 0; k < KNN; ++k) { fd[k] = CUDART_INF_F; fi[k] = 0x7fffffff; }
        float wst = CUDART_INF_F; int wsl = 0;
        for (int e = 0; e < 64; ++e) {
            float d = mdist[r * 64 + e];
            int   j = midx [r * 64 + e];
            // lexicographic filter: accept equal dist with smaller idx too
            if (d < wst || (d == wst && j < fi[wsl])) {
                #pragma unroll
                for (int k = 0; k < KNN; ++k)
                    if (k == wsl) { fd[k] = d; fi[k] = j; }
                float mv = fd[0]; int mj = fi[0]; int ms = 0;
                #pragma unroll
                for (int k = 1; k < KNN; ++k) {
                    bool gg = (fd[k] > mv) || (fd[k] == mv && fi[k] > mj);
                    if (gg) { mv = fd[k]; mj = fi[k]; ms = k; }
                }
                wst = mv; wsl = ms;
            }
        }
        // sort ascending (dist, idx)
        #pragma unroll
        for (int p = 0; p < KNN; ++p) {
            #pragma unroll
            for (int k = (p & 1); k + 1 < KNN; k += 2) {
                bool sw = (fd[k] > fd[k + 1]) || (fd[k] == fd[k + 1] && fi[k] > fi[k + 1]);
                if (sw) {
                    float td = fd[k]; fd[k] = fd[k + 1]; fd[k + 1] = td;
                    int   ti = fi[k]; fi[k] = fi[k + 1]; fi[k + 1] = ti;
                }
            }
        }
        // emit [knn_dist | dst | src]
        const int    i    = i0 + r;
        const size_t row  = (size_t)b * NP + i;
        const size_t sect = (size_t)NS * NP * KNN;
        float* od   = out + row * KNN;
        float* odst = out + sect + row * KNN;
        float* osrc = out + 2 * sect + row * KNN;
        const int off = b * NP;
        #pragma unroll
        for (int k = 0; k < KNN; ++k) {
            od[k]   = fd[k];
            odst[k] = (float)(fi[k] + off);
            osrc[k] = (float)(i + off);
        }
    }
}

extern "C" void kernel_launch(void* const* d_in, const int* in_sizes, int n_in,
                              void* d_out, int out_size) {
    (void)in_sizes; (void)n_in; (void)out_size;
    const float* h = (const float*)d_in[0];   // (16, 2048, 64) fp32; K=16 hardcoded
    float* out = (float*)d_out;
    dim3 grid(NS, NP / IM);
    knn_hmma_kernel<<<grid, 128>>>(h, out);
}